// round 15
// baseline (speedup 1.0000x reference)
#include <cuda_runtime.h>
#include <cuda_bf16.h>
#include <cuda_fp16.h>
#include <mma.h>
#include <cstdint>

using namespace nvcuda;

#define NN 50000
#define NR 50048   // padded rows (multiple of 64) for unguarded tile stores
#define EE 800000
#define DIN 128
#define DHID 128
#define DOUT 64
#define NBLK 196   // ceil(NN/256)

// ---------------- device scratch ----------------
__device__ int   g_is64;
__device__ int   g_deg[NN];
__device__ int   g_cur[NN];
__device__ int   g_off[NN + 1];
__device__ int   g_bsum[NBLK];
__device__ int   g_boff[NBLK];
__device__ int   g_src[EE];
__device__ __align__(16) __half g_ylh[(size_t)NR * 128]; // x@W1l in fp16 (gathered by agg1)
__device__ __align__(16) float  g_yr [(size_t)NR * 128]; // x@W1r fp32 (self term)
__device__ __align__(16) float  g_h  [(size_t)NR * 128]; // layer1 activations
__device__ __align__(16) __half g_zlh[(size_t)NR * 64];  // h@W2l in fp16 (gathered by agg2)
__device__ __align__(16) float  g_zr [(size_t)NR * 64];  // h@W2r fp32 (self term)
// split-bf16 weights, [K][OCT] row-major
__device__ __align__(16) __nv_bfloat16 g_w1hi[128 * 256];
__device__ __align__(16) __nv_bfloat16 g_w1lo[128 * 256];
__device__ __align__(16) __nv_bfloat16 g_w2hi[128 * 128];
__device__ __align__(16) __nv_bfloat16 g_w2lo[128 * 128];

// ---------------- dtype detect ----------------
__global__ void detect_kernel(const void* ei) {
    if (threadIdx.x == 0 && blockIdx.x == 0) {
        const long long* p = (const long long*)ei;
        int ok = 1;
        for (int i = 0; i < 256; i++) { long long v = p[i]; if (v < 0 || v >= NN) { ok = 0; break; } }
        g_is64 = ok;
    }
}

// ---------------- CSR build ----------------
__global__ void zero_counts() {
    int i = blockIdx.x * blockDim.x + threadIdx.x;
    if (i < NN) { g_deg[i] = 0; g_cur[i] = 0; }
}
__global__ void hist_kernel(const void* eiv) {
    int e = blockIdx.x * blockDim.x + threadIdx.x;
    if (e < EE) {
        long long d = g_is64 ? ((const long long*)eiv)[EE + e] : (long long)((const int*)eiv)[EE + e];
        if ((unsigned long long)d < NN) atomicAdd(&g_deg[(int)d], 1);
    }
}
__global__ void scan1() {
    __shared__ int ws[8], woff[8];
    int b = blockIdx.x, t = threadIdx.x, i = b * 256 + t;
    int v = (i < NN) ? g_deg[i] : 0;
    int lane = t & 31, w = t >> 5;
    int s = v;
    #pragma unroll
    for (int d = 1; d < 32; d <<= 1) { int n = __shfl_up_sync(0xffffffffu, s, d); if (lane >= d) s += n; }
    if (lane == 31) ws[w] = s;
    __syncthreads();
    if (t == 0) { int acc = 0; for (int j = 0; j < 8; j++) { woff[j] = acc; acc += ws[j]; } g_bsum[b] = acc; }
    __syncthreads();
    if (i < NN) g_off[i] = woff[w] + s - v;
}
__global__ void scan2() {
    __shared__ int ws[8], woff[8];
    int t = threadIdx.x;
    int v = (t < NBLK) ? g_bsum[t] : 0;
    int lane = t & 31, w = t >> 5;
    int s = v;
    #pragma unroll
    for (int d = 1; d < 32; d <<= 1) { int n = __shfl_up_sync(0xffffffffu, s, d); if (lane >= d) s += n; }
    if (lane == 31) ws[w] = s;
    __syncthreads();
    if (t == 0) { int acc = 0; for (int j = 0; j < 8; j++) { woff[j] = acc; acc += ws[j]; } g_off[NN] = acc; }
    __syncthreads();
    if (t < NBLK) g_boff[t] = woff[w] + s - v;
}
__global__ void scan3() {
    int i = blockIdx.x * blockDim.x + threadIdx.x;
    if (i < NN) g_off[i] += g_boff[i >> 8];
}
__global__ void fill_kernel(const void* eiv) {
    int e = blockIdx.x * blockDim.x + threadIdx.x;
    if (e < EE) {
        long long s, d;
        if (g_is64) { s = ((const long long*)eiv)[e]; d = ((const long long*)eiv)[EE + e]; }
        else        { s = ((const int*)eiv)[e];       d = ((const int*)eiv)[EE + e]; }
        if ((unsigned long long)s < NN && (unsigned long long)d < NN) {
            int pos = g_off[(int)d] + atomicAdd(&g_cur[(int)d], 1);
            if ((unsigned)pos < EE) g_src[pos] = (int)s;
        }
    }
}

// ---------------- weight prep: split bf16, [K][OCT] row-major ----------------
__global__ void prep_w(const float* __restrict__ W1l, const float* __restrict__ W1r,
                       const float* __restrict__ W2l, const float* __restrict__ W2r) {
    int idx = blockIdx.x * blockDim.x + threadIdx.x;
    if (idx >= 128 * 256 + 128 * 128) return;
    float w;
    __nv_bfloat16 *dh, *dl;
    if (idx < 128 * 256) {
        int k = idx >> 8, c = idx & 255;
        w = (c < 128) ? W1l[k * 128 + c] : W1r[k * 128 + (c - 128)];
        dh = g_w1hi + idx; dl = g_w1lo + idx;
    } else {
        int e = idx - 128 * 256;
        int k = e >> 7, c = e & 127;
        w = (c < 64) ? W2l[k * 64 + c] : W2r[k * 64 + (c - 64)];
        dh = g_w2hi + e; dl = g_w2lo + e;
    }
    __nv_bfloat16 hi = __float2bfloat16(w);
    __nv_bfloat16 lo = __float2bfloat16(w - __bfloat162float(hi));
    *dh = hi; *dl = lo;
}

// ---------------- WMMA bf16 split GEMM (v2 + split fp16/fp32 epilogue) ----------------
// Block: 64 rows, c-loop over 128-col chunks of OCT. X split once per block.
// 8 warps = 2 row-groups x 4 col-groups; warp tile 32x32 (2x2 accum frags).
// Cols [0,HALFC) -> fp16 buffer Yh (stride HALFC); cols [HALFC,OCT) -> fp32 Yf (stride OCT-HALFC).
// Smem: xhi/xlo [64][136] + whi/wlo [128][136] bf16 = 104448 B -> 2 blocks/SM.
template <int OCT, int HALFC>
__global__ void __launch_bounds__(256) gemm_wmma(const float* __restrict__ X,
                                                 const __nv_bfloat16* __restrict__ Whi,
                                                 const __nv_bfloat16* __restrict__ Wlo,
                                                 __half* __restrict__ Yh,
                                                 float* __restrict__ Yf, int nrows) {
    extern __shared__ unsigned char sm[];
    __nv_bfloat16* xhi = (__nv_bfloat16*)sm;            // 64*136
    __nv_bfloat16* xlo = xhi + 64 * 136;
    __nv_bfloat16* whs = xlo + 64 * 136;                // 128*136
    __nv_bfloat16* wls = whs + 128 * 136;

    int r0 = blockIdx.x * 64;
    int tid = threadIdx.x;

    // load + split X tile (64 rows x 128 k) ONCE
    for (int i = tid; i < 64 * 32; i += 256) {
        int r = i >> 5, q = i & 31;
        float4 v = make_float4(0.f, 0.f, 0.f, 0.f);
        if (r0 + r < nrows) v = ((const float4*)X)[(size_t)(r0 + r) * 32 + q];
        __nv_bfloat16 h0 = __float2bfloat16(v.x), h1 = __float2bfloat16(v.y);
        __nv_bfloat16 h2 = __float2bfloat16(v.z), h3 = __float2bfloat16(v.w);
        __nv_bfloat16 l0 = __float2bfloat16(v.x - __bfloat162float(h0));
        __nv_bfloat16 l1 = __float2bfloat16(v.y - __bfloat162float(h1));
        __nv_bfloat16 l2 = __float2bfloat16(v.z - __bfloat162float(h2));
        __nv_bfloat16 l3 = __float2bfloat16(v.w - __bfloat162float(h3));
        int base = r * 136 + q * 4;
        xhi[base] = h0; xhi[base + 1] = h1; xhi[base + 2] = h2; xhi[base + 3] = h3;
        xlo[base] = l0; xlo[base + 1] = l1; xlo[base + 2] = l2; xlo[base + 3] = l3;
    }

    int wid = tid >> 5;
    int wr = (wid & 1) * 32;        // warp row offset
    int wc = (wid >> 1) * 32;       // warp col offset within 128-col chunk

    #pragma unroll
    for (int c0 = 0; c0 < OCT; c0 += 128) {
        __syncthreads();   // X ready (iter 0) / prior-iter epilogue reads done
        // load W chunk: 128 k x 128 cols, hi+lo (uint2 = 4 bf16)
        for (int i = tid; i < 128 * 32; i += 256) {
            int k = i >> 5, q = i & 31;
            *(uint2*)&whs[k * 136 + q * 4] = *(const uint2*)(Whi + (size_t)k * OCT + c0 + q * 4);
            *(uint2*)&wls[k * 136 + q * 4] = *(const uint2*)(Wlo + (size_t)k * OCT + c0 + q * 4);
        }
        __syncthreads();

        wmma::fragment<wmma::accumulator, 16, 16, 16, float> acc[2][2];
        wmma::fill_fragment(acc[0][0], 0.f);
        wmma::fill_fragment(acc[0][1], 0.f);
        wmma::fill_fragment(acc[1][0], 0.f);
        wmma::fill_fragment(acc[1][1], 0.f);

        #pragma unroll
        for (int k = 0; k < 8; k++) {
            wmma::fragment<wmma::matrix_a, 16, 16, 16, __nv_bfloat16, wmma::row_major> ah[2], al[2];
            wmma::fragment<wmma::matrix_b, 16, 16, 16, __nv_bfloat16, wmma::row_major> bh[2], bl[2];
            wmma::load_matrix_sync(ah[0], xhi + (size_t)wr * 136 + k * 16, 136);
            wmma::load_matrix_sync(ah[1], xhi + (size_t)(wr + 16) * 136 + k * 16, 136);
            wmma::load_matrix_sync(al[0], xlo + (size_t)wr * 136 + k * 16, 136);
            wmma::load_matrix_sync(al[1], xlo + (size_t)(wr + 16) * 136 + k * 16, 136);
            wmma::load_matrix_sync(bh[0], whs + (size_t)(k * 16) * 136 + wc, 136);
            wmma::load_matrix_sync(bh[1], whs + (size_t)(k * 16) * 136 + wc + 16, 136);
            wmma::load_matrix_sync(bl[0], wls + (size_t)(k * 16) * 136 + wc, 136);
            wmma::load_matrix_sync(bl[1], wls + (size_t)(k * 16) * 136 + wc + 16, 136);
            #pragma unroll
            for (int i = 0; i < 2; i++)
                #pragma unroll
                for (int j = 0; j < 2; j++) {
                    wmma::mma_sync(acc[i][j], ah[i], bh[j], acc[i][j]);
                    wmma::mma_sync(acc[i][j], ah[i], bl[j], acc[i][j]);
                    wmma::mma_sync(acc[i][j], al[i], bh[j], acc[i][j]);
                }
        }

        // epilogue: stage f32 block in whs (B reads done), then split-write fp16/fp32
        __syncthreads();
        float* stage = (float*)whs;   // 64 x 132 f32 = 33792 B <= 34816 B (whs)
        #pragma unroll
        for (int i = 0; i < 2; i++)
            #pragma unroll
            for (int j = 0; j < 2; j++)
                wmma::store_matrix_sync(stage + (size_t)(wr + i * 16) * 132 + wc + j * 16,
                                        acc[i][j], 132, wmma::mem_row_major);
        __syncthreads();
        for (int i = tid; i < 64 * 32; i += 256) {
            int r = i >> 5, q = i & 31;         // q = group of 4 cols
            int c = c0 + q * 4;
            const float* sp = stage + r * 132 + q * 4;
            if (c < HALFC) {
                __half2 h0 = __floats2half2_rn(sp[0], sp[1]);
                __half2 h1 = __floats2half2_rn(sp[2], sp[3]);
                uint2 u;
                u.x = *(uint32_t*)&h0;
                u.y = *(uint32_t*)&h1;
                *(uint2*)(Yh + (size_t)(r0 + r) * HALFC + c) = u;
            } else {
                float4 f = make_float4(sp[0], sp[1], sp[2], sp[3]);
                *(float4*)(Yf + (size_t)(r0 + r) * (OCT - HALFC) + (c - HALFC)) = f;
            }
        }
    }
}

// ---------------- aggregation (pull, warp-per-node; fp16 gather, fp32 accumulate) ----------------
__global__ void agg1_kernel(const float* __restrict__ b1) {
    int n = blockIdx.x, t = threadIdx.x;  // 32 lanes, 4 cols each (128 cols)
    int beg = g_off[n], end = g_off[n + 1];
    float4 a = make_float4(0.f, 0.f, 0.f, 0.f);
    int k = beg;
    for (; k + 3 < end; k += 4) {
        int s0 = g_src[k], s1 = g_src[k + 1], s2 = g_src[k + 2], s3 = g_src[k + 3];
        uint2 u0 = *(const uint2*)(g_ylh + (size_t)s0 * 128 + t * 4);
        uint2 u1 = *(const uint2*)(g_ylh + (size_t)s1 * 128 + t * 4);
        uint2 u2 = *(const uint2*)(g_ylh + (size_t)s2 * 128 + t * 4);
        uint2 u3 = *(const uint2*)(g_ylh + (size_t)s3 * 128 + t * 4);
        #pragma unroll
        for (int j = 0; j < 4; j++) {
            uint2 u = (j == 0) ? u0 : (j == 1) ? u1 : (j == 2) ? u2 : u3;
            float2 f0 = __half22float2(*(__half2*)&u.x);
            float2 f1 = __half22float2(*(__half2*)&u.y);
            a.x += f0.x; a.y += f0.y; a.z += f1.x; a.w += f1.y;
        }
    }
    for (; k < end; k++) {
        uint2 u = *(const uint2*)(g_ylh + (size_t)g_src[k] * 128 + t * 4);
        float2 f0 = __half22float2(*(__half2*)&u.x);
        float2 f1 = __half22float2(*(__half2*)&u.y);
        a.x += f0.x; a.y += f0.y; a.z += f1.x; a.w += f1.y;
    }
    int deg = end - beg;
    float inv = 1.0f / ((deg > 0) ? (float)deg : 1.0f);
    float4 self = *(const float4*)(g_yr + (size_t)n * 128 + t * 4);
    float4 bb = ((const float4*)b1)[t];
    float4 r;
    r.x = fmaxf(a.x * inv + bb.x + self.x, 0.f);
    r.y = fmaxf(a.y * inv + bb.y + self.y, 0.f);
    r.z = fmaxf(a.z * inv + bb.z + self.z, 0.f);
    r.w = fmaxf(a.w * inv + bb.w + self.w, 0.f);
    *(float4*)(g_h + (size_t)n * 128 + t * 4) = r;
}

__global__ void agg2_kernel(const float* __restrict__ b2, float* __restrict__ out) {
    int n = blockIdx.x, t = threadIdx.x;  // 32 lanes, 2 cols each (64 cols)
    int beg = g_off[n], end = g_off[n + 1];
    float2 a = make_float2(0.f, 0.f);
    int k = beg;
    for (; k + 3 < end; k += 4) {
        int s0 = g_src[k], s1 = g_src[k + 1], s2 = g_src[k + 2], s3 = g_src[k + 3];
        uint32_t u0 = *(const uint32_t*)(g_zlh + (size_t)s0 * 64 + t * 2);
        uint32_t u1 = *(const uint32_t*)(g_zlh + (size_t)s1 * 64 + t * 2);
        uint32_t u2 = *(const uint32_t*)(g_zlh + (size_t)s2 * 64 + t * 2);
        uint32_t u3 = *(const uint32_t*)(g_zlh + (size_t)s3 * 64 + t * 2);
        float2 f0 = __half22float2(*(__half2*)&u0);
        float2 f1 = __half22float2(*(__half2*)&u1);
        float2 f2 = __half22float2(*(__half2*)&u2);
        float2 f3 = __half22float2(*(__half2*)&u3);
        a.x += f0.x + f1.x + f2.x + f3.x;
        a.y += f0.y + f1.y + f2.y + f3.y;
    }
    for (; k < end; k++) {
        uint32_t u = *(const uint32_t*)(g_zlh + (size_t)g_src[k] * 64 + t * 2);
        float2 f = __half22float2(*(__half2*)&u);
        a.x += f.x; a.y += f.y;
    }
    int deg = end - beg;
    float inv = 1.0f / ((deg > 0) ? (float)deg : 1.0f);
    float2 self = *(const float2*)(g_zr + (size_t)n * 64 + t * 2);
    float2 bb = ((const float2*)b2)[t];
    float2 r;
    r.x = a.x * inv + bb.x + self.x;
    r.y = a.y * inv + bb.y + self.y;
    ((float2*)out)[(size_t)n * 32 + t] = r;
}

// ---------------- launch ----------------
extern "C" void kernel_launch(void* const* d_in, const int* in_sizes, int n_in,
                              void* d_out, int out_size) {
    const float *x = 0, *W1l = 0, *b1 = 0, *W1r = 0, *W2l = 0, *b2 = 0, *W2r = 0;
    const void* ei = 0;
    for (int i = 0; i < n_in; i++) {
        int s = in_sizes[i];
        if (s == NN * DIN)            x = (const float*)d_in[i];
        else if (s == 2 * EE)         ei = d_in[i];
        else if (s == DIN * DHID)   { if (!W1l) W1l = (const float*)d_in[i]; else W1r = (const float*)d_in[i]; }
        else if (s == DHID * DOUT)  { if (!W2l) W2l = (const float*)d_in[i]; else W2r = (const float*)d_in[i]; }
        else if (s == DHID)           b1 = (const float*)d_in[i];
        else if (s == DOUT)           b2 = (const float*)d_in[i];
    }
    float* out = (float*)d_out;

    float *hp;
    __half *ylh, *zlh;
    float *yr, *zr;
    __nv_bfloat16 *w1h, *w1l_, *w2h, *w2l_;
    cudaGetSymbolAddress((void**)&ylh, g_ylh);
    cudaGetSymbolAddress((void**)&yr, g_yr);
    cudaGetSymbolAddress((void**)&hp, g_h);
    cudaGetSymbolAddress((void**)&zlh, g_zlh);
    cudaGetSymbolAddress((void**)&zr, g_zr);
    cudaGetSymbolAddress((void**)&w1h, g_w1hi);
    cudaGetSymbolAddress((void**)&w1l_, g_w1lo);
    cudaGetSymbolAddress((void**)&w2h, g_w2hi);
    cudaGetSymbolAddress((void**)&w2l_, g_w2lo);

    const int SMEM = (2 * 64 * 136 + 2 * 128 * 136) * 2;  // 104448 -> 2 blocks/SM
    cudaFuncSetAttribute((gemm_wmma<256, 128>), cudaFuncAttributeMaxDynamicSharedMemorySize, SMEM);
    cudaFuncSetAttribute((gemm_wmma<128, 64>), cudaFuncAttributeMaxDynamicSharedMemorySize, SMEM);

    // fork/join stream for gemm1 || CSR-build overlap (created once, first call is uncaptured)
    static cudaStream_t s1 = 0;
    static cudaEvent_t ev0 = 0, ev1 = 0;
    if (!s1) {
        cudaStreamCreateWithFlags(&s1, cudaStreamNonBlocking);
        cudaEventCreateWithFlags(&ev0, cudaEventDisableTiming);
        cudaEventCreateWithFlags(&ev1, cudaEventDisableTiming);
    }

    cudaEventRecord(ev0, 0);
    cudaStreamWaitEvent(s1, ev0, 0);

    prep_w<<<(128 * 256 + 128 * 128 + 255) / 256, 256>>>(W1l, W1r, W2l, W2r);
    detect_kernel<<<1, 32, 0, s1>>>(ei);
    zero_counts<<<NBLK, 256, 0, s1>>>();

    // layer 1 GEMM (stream 0) overlaps CSR build (s1)
    gemm_wmma<256, 128><<<(NN + 63) / 64, 256, SMEM>>>(x, w1h, w1l_, ylh, yr, NN);

    hist_kernel<<<(EE + 255) / 256, 256, 0, s1>>>(ei);
    scan1<<<NBLK, 256, 0, s1>>>();
    scan2<<<1, 256, 0, s1>>>();
    scan3<<<NBLK, 256, 0, s1>>>();
    fill_kernel<<<(EE + 255) / 256, 256, 0, s1>>>(ei);
    cudaEventRecord(ev1, s1);
    cudaStreamWaitEvent(0, ev1, 0);   // join: agg1 needs CSR + gemm1

    agg1_kernel<<<NN, 32>>>(b1);
    gemm_wmma<128, 64><<<(NN + 63) / 64, 256, SMEM>>>(hp, w2h, w2l_, zlh, zr, NN);
    agg2_kernel<<<NN, 32>>>(b2, out);
}

// round 16
// speedup vs baseline: 1.1546x; 1.1546x over previous
#include <cuda_runtime.h>
#include <cuda_bf16.h>
#include <cuda_fp16.h>
#include <mma.h>
#include <cstdint>

using namespace nvcuda;

#define NN 50000
#define NR 50048   // padded rows (multiple of 64) for unguarded tile stores
#define EE 800000
#define DIN 128
#define DHID 128
#define DOUT 64
#define NBLK 196   // ceil(NN/256)

// ---------------- device scratch ----------------
__device__ int   g_is64;
__device__ int   g_deg[NN];
__device__ int   g_cur[NN];
__device__ int   g_off[NN + 1];
__device__ int   g_bsum[NBLK];
__device__ int   g_boff[NBLK];
__device__ int   g_src[EE];
__device__ __align__(16) __half g_ylh[(size_t)NR * 128]; // x@W1l in fp16 (gathered by agg1)
__device__ __align__(16) float  g_yr [(size_t)NR * 128]; // x@W1r fp32 (self term)
__device__ __align__(16) float  g_h  [(size_t)NR * 128]; // layer1 activations
__device__ __align__(16) __half g_zlh[(size_t)NR * 64];  // h@W2l in fp16 (gathered by agg2)
__device__ __align__(16) float  g_zr [(size_t)NR * 64];  // h@W2r fp32 (self term)
// split-bf16 weights, [K][OCT] row-major
__device__ __align__(16) __nv_bfloat16 g_w1hi[128 * 256];
__device__ __align__(16) __nv_bfloat16 g_w1lo[128 * 256];
__device__ __align__(16) __nv_bfloat16 g_w2hi[128 * 128];
__device__ __align__(16) __nv_bfloat16 g_w2lo[128 * 128];

// ---------------- dtype detect ----------------
__global__ void detect_kernel(const void* ei) {
    if (threadIdx.x == 0 && blockIdx.x == 0) {
        const long long* p = (const long long*)ei;
        int ok = 1;
        for (int i = 0; i < 256; i++) { long long v = p[i]; if (v < 0 || v >= NN) { ok = 0; break; } }
        g_is64 = ok;
    }
}

// ---------------- CSR build ----------------
__global__ void zero_counts() {
    int i = blockIdx.x * blockDim.x + threadIdx.x;
    if (i < NN) { g_deg[i] = 0; g_cur[i] = 0; }
}
__global__ void hist_kernel(const void* eiv) {
    int e = blockIdx.x * blockDim.x + threadIdx.x;
    if (e < EE) {
        long long d = g_is64 ? ((const long long*)eiv)[EE + e] : (long long)((const int*)eiv)[EE + e];
        if ((unsigned long long)d < NN) atomicAdd(&g_deg[(int)d], 1);
    }
}
__global__ void scan1() {
    __shared__ int ws[8], woff[8];
    int b = blockIdx.x, t = threadIdx.x, i = b * 256 + t;
    int v = (i < NN) ? g_deg[i] : 0;
    int lane = t & 31, w = t >> 5;
    int s = v;
    #pragma unroll
    for (int d = 1; d < 32; d <<= 1) { int n = __shfl_up_sync(0xffffffffu, s, d); if (lane >= d) s += n; }
    if (lane == 31) ws[w] = s;
    __syncthreads();
    if (t == 0) { int acc = 0; for (int j = 0; j < 8; j++) { woff[j] = acc; acc += ws[j]; } g_bsum[b] = acc; }
    __syncthreads();
    if (i < NN) g_off[i] = woff[w] + s - v;
}
__global__ void scan2() {
    __shared__ int ws[8], woff[8];
    int t = threadIdx.x;
    int v = (t < NBLK) ? g_bsum[t] : 0;
    int lane = t & 31, w = t >> 5;
    int s = v;
    #pragma unroll
    for (int d = 1; d < 32; d <<= 1) { int n = __shfl_up_sync(0xffffffffu, s, d); if (lane >= d) s += n; }
    if (lane == 31) ws[w] = s;
    __syncthreads();
    if (t == 0) { int acc = 0; for (int j = 0; j < 8; j++) { woff[j] = acc; acc += ws[j]; } g_off[NN] = acc; }
    __syncthreads();
    if (t < NBLK) g_boff[t] = woff[w] + s - v;
}
__global__ void scan3() {
    int i = blockIdx.x * blockDim.x + threadIdx.x;
    if (i < NN) g_off[i] += g_boff[i >> 8];
}
__global__ void fill_kernel(const void* eiv) {
    int e = blockIdx.x * blockDim.x + threadIdx.x;
    if (e < EE) {
        long long s, d;
        if (g_is64) { s = ((const long long*)eiv)[e]; d = ((const long long*)eiv)[EE + e]; }
        else        { s = ((const int*)eiv)[e];       d = ((const int*)eiv)[EE + e]; }
        if ((unsigned long long)s < NN && (unsigned long long)d < NN) {
            int pos = g_off[(int)d] + atomicAdd(&g_cur[(int)d], 1);
            if ((unsigned)pos < EE) g_src[pos] = (int)s;
        }
    }
}

// ---------------- weight prep: split bf16, [K][OCT] row-major ----------------
__global__ void prep_w(const float* __restrict__ W1l, const float* __restrict__ W1r,
                       const float* __restrict__ W2l, const float* __restrict__ W2r) {
    int idx = blockIdx.x * blockDim.x + threadIdx.x;
    if (idx >= 128 * 256 + 128 * 128) return;
    float w;
    __nv_bfloat16 *dh, *dl;
    if (idx < 128 * 256) {
        int k = idx >> 8, c = idx & 255;
        w = (c < 128) ? W1l[k * 128 + c] : W1r[k * 128 + (c - 128)];
        dh = g_w1hi + idx; dl = g_w1lo + idx;
    } else {
        int e = idx - 128 * 256;
        int k = e >> 7, c = e & 127;
        w = (c < 64) ? W2l[k * 64 + c] : W2r[k * 64 + (c - 64)];
        dh = g_w2hi + e; dl = g_w2lo + e;
    }
    __nv_bfloat16 hi = __float2bfloat16(w);
    __nv_bfloat16 lo = __float2bfloat16(w - __bfloat162float(hi));
    *dh = hi; *dl = lo;
}

// ---------------- WMMA bf16 split GEMM (v2 + split fp16/fp32 epilogue) ----------------
template <int OCT, int HALFC>
__global__ void __launch_bounds__(256) gemm_wmma(const float* __restrict__ X,
                                                 const __nv_bfloat16* __restrict__ Whi,
                                                 const __nv_bfloat16* __restrict__ Wlo,
                                                 __half* __restrict__ Yh,
                                                 float* __restrict__ Yf, int nrows) {
    extern __shared__ unsigned char sm[];
    __nv_bfloat16* xhi = (__nv_bfloat16*)sm;            // 64*136
    __nv_bfloat16* xlo = xhi + 64 * 136;
    __nv_bfloat16* whs = xlo + 64 * 136;                // 128*136
    __nv_bfloat16* wls = whs + 128 * 136;

    int r0 = blockIdx.x * 64;
    int tid = threadIdx.x;

    // load + split X tile (64 rows x 128 k) ONCE
    for (int i = tid; i < 64 * 32; i += 256) {
        int r = i >> 5, q = i & 31;
        float4 v = make_float4(0.f, 0.f, 0.f, 0.f);
        if (r0 + r < nrows) v = ((const float4*)X)[(size_t)(r0 + r) * 32 + q];
        __nv_bfloat16 h0 = __float2bfloat16(v.x), h1 = __float2bfloat16(v.y);
        __nv_bfloat16 h2 = __float2bfloat16(v.z), h3 = __float2bfloat16(v.w);
        __nv_bfloat16 l0 = __float2bfloat16(v.x - __bfloat162float(h0));
        __nv_bfloat16 l1 = __float2bfloat16(v.y - __bfloat162float(h1));
        __nv_bfloat16 l2 = __float2bfloat16(v.z - __bfloat162float(h2));
        __nv_bfloat16 l3 = __float2bfloat16(v.w - __bfloat162float(h3));
        int base = r * 136 + q * 4;
        xhi[base] = h0; xhi[base + 1] = h1; xhi[base + 2] = h2; xhi[base + 3] = h3;
        xlo[base] = l0; xlo[base + 1] = l1; xlo[base + 2] = l2; xlo[base + 3] = l3;
    }

    int wid = tid >> 5;
    int wr = (wid & 1) * 32;        // warp row offset
    int wc = (wid >> 1) * 32;       // warp col offset within 128-col chunk

    #pragma unroll
    for (int c0 = 0; c0 < OCT; c0 += 128) {
        __syncthreads();   // X ready (iter 0) / prior-iter epilogue reads done
        for (int i = tid; i < 128 * 32; i += 256) {
            int k = i >> 5, q = i & 31;
            *(uint2*)&whs[k * 136 + q * 4] = *(const uint2*)(Whi + (size_t)k * OCT + c0 + q * 4);
            *(uint2*)&wls[k * 136 + q * 4] = *(const uint2*)(Wlo + (size_t)k * OCT + c0 + q * 4);
        }
        __syncthreads();

        wmma::fragment<wmma::accumulator, 16, 16, 16, float> acc[2][2];
        wmma::fill_fragment(acc[0][0], 0.f);
        wmma::fill_fragment(acc[0][1], 0.f);
        wmma::fill_fragment(acc[1][0], 0.f);
        wmma::fill_fragment(acc[1][1], 0.f);

        #pragma unroll
        for (int k = 0; k < 8; k++) {
            wmma::fragment<wmma::matrix_a, 16, 16, 16, __nv_bfloat16, wmma::row_major> ah[2], al[2];
            wmma::fragment<wmma::matrix_b, 16, 16, 16, __nv_bfloat16, wmma::row_major> bh[2], bl[2];
            wmma::load_matrix_sync(ah[0], xhi + (size_t)wr * 136 + k * 16, 136);
            wmma::load_matrix_sync(ah[1], xhi + (size_t)(wr + 16) * 136 + k * 16, 136);
            wmma::load_matrix_sync(al[0], xlo + (size_t)wr * 136 + k * 16, 136);
            wmma::load_matrix_sync(al[1], xlo + (size_t)(wr + 16) * 136 + k * 16, 136);
            wmma::load_matrix_sync(bh[0], whs + (size_t)(k * 16) * 136 + wc, 136);
            wmma::load_matrix_sync(bh[1], whs + (size_t)(k * 16) * 136 + wc + 16, 136);
            wmma::load_matrix_sync(bl[0], wls + (size_t)(k * 16) * 136 + wc, 136);
            wmma::load_matrix_sync(bl[1], wls + (size_t)(k * 16) * 136 + wc + 16, 136);
            #pragma unroll
            for (int i = 0; i < 2; i++)
                #pragma unroll
                for (int j = 0; j < 2; j++) {
                    wmma::mma_sync(acc[i][j], ah[i], bh[j], acc[i][j]);
                    wmma::mma_sync(acc[i][j], ah[i], bl[j], acc[i][j]);
                    wmma::mma_sync(acc[i][j], al[i], bh[j], acc[i][j]);
                }
        }

        // epilogue: stage f32 block in whs (B reads done), then split-write fp16/fp32
        __syncthreads();
        float* stage = (float*)whs;   // 64 x 132 f32 = 33792 B <= 34816 B (whs)
        #pragma unroll
        for (int i = 0; i < 2; i++)
            #pragma unroll
            for (int j = 0; j < 2; j++)
                wmma::store_matrix_sync(stage + (size_t)(wr + i * 16) * 132 + wc + j * 16,
                                        acc[i][j], 132, wmma::mem_row_major);
        __syncthreads();
        for (int i = tid; i < 64 * 32; i += 256) {
            int r = i >> 5, q = i & 31;         // q = group of 4 cols
            int c = c0 + q * 4;
            const float* sp = stage + r * 132 + q * 4;
            if (c < HALFC) {
                __half2 h0 = __floats2half2_rn(sp[0], sp[1]);
                __half2 h1 = __floats2half2_rn(sp[2], sp[3]);
                uint2 u;
                u.x = *(uint32_t*)&h0;
                u.y = *(uint32_t*)&h1;
                *(uint2*)(Yh + (size_t)(r0 + r) * HALFC + c) = u;
            } else {
                float4 f = make_float4(sp[0], sp[1], sp[2], sp[3]);
                *(float4*)(Yf + (size_t)(r0 + r) * (OCT - HALFC) + (c - HALFC)) = f;
            }
        }
    }
}

// ---------------- aggregation: 8 warps/block = 8 nodes/block, 8-deep gather unroll ----------------
__global__ void __launch_bounds__(256) agg1_kernel(const float* __restrict__ b1) {
    int wid = threadIdx.x >> 5, t = threadIdx.x & 31;
    int n = blockIdx.x * 8 + wid;
    if (n >= NN) return;
    int beg = g_off[n], end = g_off[n + 1];
    float4 a = make_float4(0.f, 0.f, 0.f, 0.f);
    int k = beg;
    for (; k + 7 < end; k += 8) {
        uint2 u[8];
        #pragma unroll
        for (int j = 0; j < 8; j++)
            u[j] = *(const uint2*)(g_ylh + (size_t)__ldg(&g_src[k + j]) * 128 + t * 4);
        #pragma unroll
        for (int j = 0; j < 8; j++) {
            float2 f0 = __half22float2(*(__half2*)&u[j].x);
            float2 f1 = __half22float2(*(__half2*)&u[j].y);
            a.x += f0.x; a.y += f0.y; a.z += f1.x; a.w += f1.y;
        }
    }
    for (; k + 3 < end; k += 4) {
        uint2 u[4];
        #pragma unroll
        for (int j = 0; j < 4; j++)
            u[j] = *(const uint2*)(g_ylh + (size_t)__ldg(&g_src[k + j]) * 128 + t * 4);
        #pragma unroll
        for (int j = 0; j < 4; j++) {
            float2 f0 = __half22float2(*(__half2*)&u[j].x);
            float2 f1 = __half22float2(*(__half2*)&u[j].y);
            a.x += f0.x; a.y += f0.y; a.z += f1.x; a.w += f1.y;
        }
    }
    for (; k < end; k++) {
        uint2 u = *(const uint2*)(g_ylh + (size_t)__ldg(&g_src[k]) * 128 + t * 4);
        float2 f0 = __half22float2(*(__half2*)&u.x);
        float2 f1 = __half22float2(*(__half2*)&u.y);
        a.x += f0.x; a.y += f0.y; a.z += f1.x; a.w += f1.y;
    }
    int deg = end - beg;
    float inv = 1.0f / ((deg > 0) ? (float)deg : 1.0f);
    float4 self = *(const float4*)(g_yr + (size_t)n * 128 + t * 4);
    float4 bb = ((const float4*)b1)[t];
    float4 r;
    r.x = fmaxf(a.x * inv + bb.x + self.x, 0.f);
    r.y = fmaxf(a.y * inv + bb.y + self.y, 0.f);
    r.z = fmaxf(a.z * inv + bb.z + self.z, 0.f);
    r.w = fmaxf(a.w * inv + bb.w + self.w, 0.f);
    *(float4*)(g_h + (size_t)n * 128 + t * 4) = r;
}

__global__ void __launch_bounds__(256) agg2_kernel(const float* __restrict__ b2, float* __restrict__ out) {
    int wid = threadIdx.x >> 5, t = threadIdx.x & 31;
    int n = blockIdx.x * 8 + wid;
    if (n >= NN) return;
    int beg = g_off[n], end = g_off[n + 1];
    float2 a = make_float2(0.f, 0.f);
    int k = beg;
    for (; k + 7 < end; k += 8) {
        uint32_t u[8];
        #pragma unroll
        for (int j = 0; j < 8; j++)
            u[j] = *(const uint32_t*)(g_zlh + (size_t)__ldg(&g_src[k + j]) * 64 + t * 2);
        #pragma unroll
        for (int j = 0; j < 8; j++) {
            float2 f = __half22float2(*(__half2*)&u[j]);
            a.x += f.x; a.y += f.y;
        }
    }
    for (; k + 3 < end; k += 4) {
        uint32_t u[4];
        #pragma unroll
        for (int j = 0; j < 4; j++)
            u[j] = *(const uint32_t*)(g_zlh + (size_t)__ldg(&g_src[k + j]) * 64 + t * 2);
        #pragma unroll
        for (int j = 0; j < 4; j++) {
            float2 f = __half22float2(*(__half2*)&u[j]);
            a.x += f.x; a.y += f.y;
        }
    }
    for (; k < end; k++) {
        uint32_t u = *(const uint32_t*)(g_zlh + (size_t)__ldg(&g_src[k]) * 64 + t * 2);
        float2 f = __half22float2(*(__half2*)&u);
        a.x += f.x; a.y += f.y;
    }
    int deg = end - beg;
    float inv = 1.0f / ((deg > 0) ? (float)deg : 1.0f);
    float2 self = *(const float2*)(g_zr + (size_t)n * 64 + t * 2);
    float2 bb = ((const float2*)b2)[t];
    float2 r;
    r.x = a.x * inv + bb.x + self.x;
    r.y = a.y * inv + bb.y + self.y;
    ((float2*)out)[(size_t)n * 32 + t] = r;
}

// ---------------- launch ----------------
extern "C" void kernel_launch(void* const* d_in, const int* in_sizes, int n_in,
                              void* d_out, int out_size) {
    const float *x = 0, *W1l = 0, *b1 = 0, *W1r = 0, *W2l = 0, *b2 = 0, *W2r = 0;
    const void* ei = 0;
    for (int i = 0; i < n_in; i++) {
        int s = in_sizes[i];
        if (s == NN * DIN)            x = (const float*)d_in[i];
        else if (s == 2 * EE)         ei = d_in[i];
        else if (s == DIN * DHID)   { if (!W1l) W1l = (const float*)d_in[i]; else W1r = (const float*)d_in[i]; }
        else if (s == DHID * DOUT)  { if (!W2l) W2l = (const float*)d_in[i]; else W2r = (const float*)d_in[i]; }
        else if (s == DHID)           b1 = (const float*)d_in[i];
        else if (s == DOUT)           b2 = (const float*)d_in[i];
    }
    float* out = (float*)d_out;

    float *hp;
    __half *ylh, *zlh;
    float *yr, *zr;
    __nv_bfloat16 *w1h, *w1l_, *w2h, *w2l_;
    cudaGetSymbolAddress((void**)&ylh, g_ylh);
    cudaGetSymbolAddress((void**)&yr, g_yr);
    cudaGetSymbolAddress((void**)&hp, g_h);
    cudaGetSymbolAddress((void**)&zlh, g_zlh);
    cudaGetSymbolAddress((void**)&zr, g_zr);
    cudaGetSymbolAddress((void**)&w1h, g_w1hi);
    cudaGetSymbolAddress((void**)&w1l_, g_w1lo);
    cudaGetSymbolAddress((void**)&w2h, g_w2hi);
    cudaGetSymbolAddress((void**)&w2l_, g_w2lo);

    const int SMEM = (2 * 64 * 136 + 2 * 128 * 136) * 2;  // 104448 -> 2 blocks/SM
    cudaFuncSetAttribute((gemm_wmma<256, 128>), cudaFuncAttributeMaxDynamicSharedMemorySize, SMEM);
    cudaFuncSetAttribute((gemm_wmma<128, 64>), cudaFuncAttributeMaxDynamicSharedMemorySize, SMEM);

    // fork/join stream for gemm1 || CSR-build overlap (created once, first call is uncaptured)
    static cudaStream_t s1 = 0;
    static cudaEvent_t ev0 = 0, ev1 = 0;
    if (!s1) {
        cudaStreamCreateWithFlags(&s1, cudaStreamNonBlocking);
        cudaEventCreateWithFlags(&ev0, cudaEventDisableTiming);
        cudaEventCreateWithFlags(&ev1, cudaEventDisableTiming);
    }

    cudaEventRecord(ev0, 0);
    cudaStreamWaitEvent(s1, ev0, 0);

    prep_w<<<(128 * 256 + 128 * 128 + 255) / 256, 256>>>(W1l, W1r, W2l, W2r);
    detect_kernel<<<1, 32, 0, s1>>>(ei);
    zero_counts<<<NBLK, 256, 0, s1>>>();

    // layer 1 GEMM (stream 0) overlaps CSR build (s1)
    gemm_wmma<256, 128><<<(NN + 63) / 64, 256, SMEM>>>(x, w1h, w1l_, ylh, yr, NN);

    hist_kernel<<<(EE + 255) / 256, 256, 0, s1>>>(ei);
    scan1<<<NBLK, 256, 0, s1>>>();
    scan2<<<1, 256, 0, s1>>>();
    scan3<<<NBLK, 256, 0, s1>>>();
    fill_kernel<<<(EE + 255) / 256, 256, 0, s1>>>(ei);
    cudaEventRecord(ev1, s1);
    cudaStreamWaitEvent(0, ev1, 0);   // join: agg1 needs CSR + gemm1

    agg1_kernel<<<(NN + 7) / 8, 256>>>(b1);
    gemm_wmma<128, 64><<<(NN + 63) / 64, 256, SMEM>>>(hp, w2h, w2l_, zlh, zr, NN);
    agg2_kernel<<<(NN + 7) / 8, 256>>>(b2, out);
}